// round 16
// baseline (speedup 1.0000x reference)
#include <cuda_runtime.h>
#include <cuda_bf16.h>
#include <math.h>

#define BB 32
#define HH 480
#define WW 640
#define HW (HH*WW)
#define HWQ (HW/4)
#define OH 34
#define OW 45
#define NC (OH*OW)      // 1530
#define K_TOP 153
#define KS 25
#define PS (KS*KS)      // 625
#define EPSV 1e-5f
#define SEG 64
#define CAPSEG (HW/SEG)     // 4800 elems per passA block region
#define CAPW (CAPSEG/8)     // 600 per warp
#define NSEGW (SEG*8)       // 512 warp segments per (a,b)
#define SAMP 16384
#define NCLUS 1024
#define CSTRIDE (HW/NCLUS)  // 300 floats between cluster starts (1200B, 16B aligned)
#define NBIN 4096

// ---------------- device scratch ----------------
__device__ unsigned g_klo[2][BB], g_khi[2][BB];
__device__ unsigned g_cnt_lt[2][BB], g_cnt_gt[2][BB];
__device__ double   g_sum_lt[2][BB], g_sum_gt[2][BB];
__device__ unsigned g_wcnt[2][BB][NSEGW];
__device__ unsigned g_compact[2][BB][HW];
__device__ float    g_med[2][BB], g_scale[2][BB];
__device__ unsigned g_ntot[2][BB];
__device__ float    g_gsum[BB], g_epsum[BB];
__device__ unsigned g_epcnt[BB];
__device__ int      g_mmode;
__device__ int      g_cy[BB][K_TOP], g_cx[BB][K_TOP];

// ---------------- helpers ----------------
__device__ __forceinline__ unsigned fkey(float v){
    unsigned u = __float_as_uint(v);
    return (u & 0x80000000u) ? ~u : (u | 0x80000000u);
}
__device__ __forceinline__ float fval(unsigned u){
    unsigned o = (u & 0x80000000u) ? (u & 0x7fffffffu) : ~u;
    return __uint_as_float(o);
}
__device__ __forceinline__ bool readmask(const void* p, size_t i, int mode){
    if (mode == 0) return ((const unsigned char*)p)[i] != 0;
    if (mode == 1) return ((const float*)p)[i] != 0.0f;
    return ((const int*)p)[i] != 0;
}
__device__ __forceinline__ unsigned keybin(unsigned key, unsigned klo, float scale){
    return min((unsigned)(NBIN-1), (unsigned)((float)(key - klo) * scale));
}

template<int NW>
__device__ __forceinline__ float bRSumF(float v, float* sh){
    int lane = threadIdx.x & 31, w = threadIdx.x >> 5;
#pragma unroll
    for (int o=16;o>0;o>>=1) v += __shfl_down_sync(0xffffffffu, v, o);
    if (lane==0) sh[w]=v;
    __syncthreads();
    if (w==0){
        float r = (lane<NW)? sh[lane]:0.f;
#pragma unroll
        for (int o=NW>>1;o>0;o>>=1) r += __shfl_down_sync(0xffffffffu, r, o);
        if (lane==0) sh[0]=r;
    }
    __syncthreads();
    float r = sh[0];
    __syncthreads();
    return r;
}
template<int NW>
__device__ __forceinline__ unsigned bRSumU(unsigned v, unsigned* sh){
    int lane = threadIdx.x & 31, w = threadIdx.x >> 5;
#pragma unroll
    for (int o=16;o>0;o>>=1) v += __shfl_down_sync(0xffffffffu, v, o);
    if (lane==0) sh[w]=v;
    __syncthreads();
    if (w==0){
        unsigned r = (lane<NW)? sh[lane]:0u;
#pragma unroll
        for (int o=NW>>1;o>0;o>>=1) r += __shfl_down_sync(0xffffffffu, r, o);
        if (lane==0) sh[0]=r;
    }
    __syncthreads();
    unsigned r = sh[0];
    __syncthreads();
    return r;
}
template<int NW>
__device__ __forceinline__ unsigned bRMinU(unsigned v, unsigned* sh){
    int lane = threadIdx.x & 31, w = threadIdx.x >> 5;
#pragma unroll
    for (int o=16;o>0;o>>=1) v = min(v, __shfl_down_sync(0xffffffffu, v, o));
    if (lane==0) sh[w]=v;
    __syncthreads();
    if (w==0){
        unsigned r = (lane<NW)? sh[lane]:0xFFFFFFFFu;
#pragma unroll
        for (int o=NW>>1;o>0;o>>=1) r = min(r, __shfl_down_sync(0xffffffffu, r, o));
        if (lane==0) sh[0]=r;
    }
    __syncthreads();
    unsigned r = sh[0];
    __syncthreads();
    return r;
}
template<int NW>
__device__ __forceinline__ unsigned bRMaxU(unsigned v, unsigned* sh){
    int lane = threadIdx.x & 31, w = threadIdx.x >> 5;
#pragma unroll
    for (int o=16;o>0;o>>=1) v = max(v, __shfl_down_sync(0xffffffffu, v, o));
    if (lane==0) sh[w]=v;
    __syncthreads();
    if (w==0){
        unsigned r = (lane<NW)? sh[lane]:0u;
#pragma unroll
        for (int o=NW>>1;o>0;o>>=1) r = max(r, __shfl_down_sync(0xffffffffu, r, o));
        if (lane==0) sh[0]=r;
    }
    __syncthreads();
    unsigned r = sh[0];
    __syncthreads();
    return r;
}
template<int NW>
__device__ __forceinline__ double bRSumD(double v, double* sh){
    int lane = threadIdx.x & 31, w = threadIdx.x >> 5;
#pragma unroll
    for (int o=16;o>0;o>>=1) v += __shfl_down_sync(0xffffffffu, v, o);
    if (lane==0) sh[w]=v;
    __syncthreads();
    if (w==0){
        double r = (lane<NW)? sh[lane]:0.0;
#pragma unroll
        for (int o=NW>>1;o>0;o>>=1) r += __shfl_down_sync(0xffffffffu, r, o);
        if (lane==0) sh[0]=r;
    }
    __syncthreads();
    double r = sh[0];
    __syncthreads();
    return r;
}
template<int NW>
__device__ __forceinline__ unsigned bScanInc(unsigned v, unsigned* sh){
    int lane = threadIdx.x & 31, w = threadIdx.x >> 5;
    unsigned x = v;
#pragma unroll
    for (int o=1;o<32;o<<=1){ unsigned t=__shfl_up_sync(0xffffffffu,x,o); if(lane>=o) x+=t; }
    if (lane==31) sh[w]=x;
    __syncthreads();
    if (w==0){
        unsigned y = (lane<NW)? sh[lane]:0u;
#pragma unroll
        for (int o=1;o<NW;o<<=1){ unsigned t=__shfl_up_sync(0xffffffffu,y,o); if(lane>=o) y+=t; }
        if (lane<NW) sh[lane]=y;
    }
    __syncthreads();
    unsigned off = (w>0)? sh[w-1]:0u;
    unsigned r = x + off;
    __syncthreads();
    return r;
}
__device__ __forceinline__ float wRSumF(float v){
#pragma unroll
    for (int o=16;o>0;o>>=1) v += __shfl_xor_sync(0xffffffffu, v, o);
    return v;
}
template<int NW>
__device__ __forceinline__ int detect_mode(const void* mask, unsigned* sh){
    const unsigned char* m = (const unsigned char*)mask;
    unsigned c=0;
    for (int i=threadIdx.x;i<4096;i+=NW*32) c += (m[i]!=0);
    c = bRSumU<NW>(c, sh);
    return (c>2765)?0 : ((c>1382)?1:2);
}

extern __shared__ unsigned sL[];

// ---------------- chain A ----------------
// clustered sampling (16384 samples) with batched independent loads; inits chain-A scratch
__global__ __launch_bounds__(256) void sample_kernel(const float* inp, const float* tgt, const void* mask){
    int a = blockIdx.x, b = blockIdx.y, tid = threadIdx.x;
    __shared__ unsigned hist[NBIN];
    __shared__ unsigned cand[1024];
    __shared__ unsigned sh8[8];
    __shared__ unsigned s_cc0, s_cc1;
    __shared__ unsigned s_bin0, s_bef0, s_bin1, s_bef1;
    __shared__ unsigned s_key0, s_key1;
    int mode = detect_mode<8>(mask, sh8);
    if (tid==0){
        if (a==0 && b==0) g_mmode = mode;
        g_cnt_lt[a][b]=0u; g_cnt_gt[a][b]=0u;
        g_sum_lt[a][b]=0.0; g_sum_gt[a][b]=0.0;
        if (a==0) g_gsum[b]=0.f;
    }
    const float* src = (a ? tgt : inp) + (size_t)b*HW;
    unsigned lc=0, lmin=0xFFFFFFFFu, lmax=0u;
    for (int c=tid; c<NCLUS; c+=256){
        int base = c*CSTRIDE;
        const float4* vp = (const float4*)(src + base);
        float4 v4[4];
#pragma unroll
        for (int q=0;q<4;q++) v4[q] = vp[q];
        bool mb[16];
        size_t mbase = (size_t)b*HW + base;
        if (mode==0){
            const uchar4* mp = (const uchar4*)((const unsigned char*)mask + mbase);
#pragma unroll
            for (int q=0;q<4;q++){ uchar4 m4=mp[q]; mb[q*4]=m4.x!=0; mb[q*4+1]=m4.y!=0; mb[q*4+2]=m4.z!=0; mb[q*4+3]=m4.w!=0; }
        } else if (mode==1){
            const float4* mp = (const float4*)((const float*)mask + mbase);
#pragma unroll
            for (int q=0;q<4;q++){ float4 m4=mp[q]; mb[q*4]=m4.x!=0.f; mb[q*4+1]=m4.y!=0.f; mb[q*4+2]=m4.z!=0.f; mb[q*4+3]=m4.w!=0.f; }
        } else {
            const int4* mp = (const int4*)((const int*)mask + mbase);
#pragma unroll
            for (int q=0;q<4;q++){ int4 m4=mp[q]; mb[q*4]=m4.x!=0; mb[q*4+1]=m4.y!=0; mb[q*4+2]=m4.z!=0; mb[q*4+3]=m4.w!=0; }
        }
        const float* vf = (const float*)v4;
#pragma unroll
        for (int j=0;j<16;j++){
            unsigned key = 0xFFFFFFFFu;
            if (mb[j]){
                key = fkey(vf[j]); lc++;
                lmin = min(lmin, key); lmax = max(lmax, key);
            }
            sL[c*16 + j] = key;
        }
    }
    for (int i=tid;i<NBIN;i+=256) hist[i]=0u;
    __syncthreads();
    unsigned ms = bRSumU<8>(lc, sh8);
    if (ms==0u){
        if (tid==0){ g_klo[a][b]=0u; g_khi[a][b]=0xFFFFFFFFu; }
        return;
    }
    unsigned kmin = bRMinU<8>(lmin, sh8);
    unsigned kmax = bRMaxU<8>(lmax, sh8);
    float scale = (float)NBIN / ((float)(kmax - kmin) + 1.0f);
    unsigned rlo = (unsigned)(0.47f*(float)ms);
    unsigned rhi = (unsigned)(0.53f*(float)ms);
    if (rhi >= ms) rhi = ms-1u;
    for (int i=tid;i<SAMP;i+=256){
        unsigned kk = sL[i];
        if (kk != 0xFFFFFFFFu) atomicAdd(&hist[keybin(kk, kmin, scale)], 1u);
    }
    if (tid==0){ s_cc0=0u; s_cc1=0u; }
    __syncthreads();
    {
        unsigned h[16], s=0;
#pragma unroll
        for (int j=0;j<16;j++){ h[j]=hist[tid*16+j]; s+=h[j]; }
        unsigned inc = bScanInc<8>(s, sh8);
        unsigned exc = inc - s;
        if (exc<=rlo && rlo<inc){
            unsigned c=exc;
#pragma unroll
            for (int j=0;j<16;j++){ if (rlo < c+h[j]){ s_bin0=tid*16+j; s_bef0=c; break; } c+=h[j]; }
        }
        if (exc<=rhi && rhi<inc){
            unsigned c=exc;
#pragma unroll
            for (int j=0;j<16;j++){ if (rhi < c+h[j]){ s_bin1=tid*16+j; s_bef1=c; break; } c+=h[j]; }
        }
    }
    __syncthreads();
    unsigned bin0=s_bin0, bin1=s_bin1;
    for (int i=tid;i<SAMP;i+=256){
        unsigned kk = sL[i];
        if (kk != 0xFFFFFFFFu){
            unsigned bn = keybin(kk, kmin, scale);
            if (bn==bin0){ unsigned p=atomicAdd(&s_cc0,1u); if (p<512u) cand[p]=kk; }
            if (bn==bin1){ unsigned p=atomicAdd(&s_cc1,1u); if (p<512u) cand[512u+p]=kk; }
        }
    }
    __syncthreads();
    unsigned cc0=s_cc0, cc1=s_cc1;
    if (cc0>512u || cc1>512u){
        if (tid==0){ g_klo[a][b]=kmin; g_khi[a][b]=kmax; }
        return;
    }
    unsigned r0 = rlo - s_bef0, r1 = rhi - s_bef1;
    for (unsigned j=tid;j<cc0;j+=256){
        unsigned kj=cand[j]; unsigned less=0,eq=0;
        for (unsigned i2=0;i2<cc0;i2++){ unsigned k2=cand[i2]; less += (k2<kj); eq += (k2==kj); }
        if (less<=r0 && r0<less+eq) s_key0=kj;
    }
    for (unsigned j=tid;j<cc1;j+=256){
        unsigned kj=cand[512u+j]; unsigned less=0,eq=0;
        for (unsigned i2=0;i2<cc1;i2++){ unsigned k2=cand[512u+i2]; less += (k2<kj); eq += (k2==kj); }
        if (less<=r1 && r1<less+eq) s_key1=kj;
    }
    __syncthreads();
    if (tid==0){ g_klo[a][b]=s_key0; g_khi[a][b]=s_key1; }
}

// one pass: counts/sums outside bracket, warp-ballot compaction inside (SEG=64 blocks/batch)
__global__ __launch_bounds__(256) void passA_kernel(const float* inp, const float* tgt, const void* mask){
    int b = blockIdx.y, blk = blockIdx.x, tid = threadIdx.x;
    int lane = tid & 31, w = tid >> 5;
    int mode = g_mmode;
    unsigned klo0=g_klo[0][b], khi0=g_khi[0][b], klo1=g_klo[1][b], khi1=g_khi[1][b];
    __shared__ unsigned sh8u[8];
    __shared__ float sh8f[8];
    const float4* ib = (const float4*)(inp + (size_t)b*HW);
    const float4* tb = (const float4*)(tgt + (size_t)b*HW);
    const int QW = HWQ/SEG/8;        // 150 float4 per warp
    int qw0 = blk*(HWQ/SEG) + w*QW;
    unsigned* out0 = &g_compact[0][b][(size_t)blk*CAPSEG + w*CAPW];
    unsigned* out1 = &g_compact[1][b][(size_t)blk*CAPSEG + w*CAPW];
    unsigned wc0=0, wc1=0;
    unsigned clt0=0,cgt0=0,clt1=0,cgt1=0;
    float slt0=0.f,sgt0=0.f,slt1=0.f,sgt1=0.f;
    unsigned lm = (1u<<lane)-1u;
    const int ITER = (QW + 31)/32;   // 5
    for (int it=0; it<ITER; it++){
        int qo = it*32 + lane;
        bool valid = (qo < QW);
        int q = qw0 + qo;
        float4 fi = {0.f,0.f,0.f,0.f}, ft = {0.f,0.f,0.f,0.f};
        bool mb[4] = {false,false,false,false};
        if (valid){
            size_t qi = (size_t)b*HWQ + q;
            if (mode==0){
                uchar4 m4 = ((const uchar4*)mask)[qi];
                mb[0]=m4.x!=0; mb[1]=m4.y!=0; mb[2]=m4.z!=0; mb[3]=m4.w!=0;
            } else if (mode==1){
                float4 m4 = ((const float4*)mask)[qi];
                mb[0]=m4.x!=0.f; mb[1]=m4.y!=0.f; mb[2]=m4.z!=0.f; mb[3]=m4.w!=0.f;
            } else {
                int4 m4 = ((const int4*)mask)[qi];
                mb[0]=m4.x!=0; mb[1]=m4.y!=0; mb[2]=m4.z!=0; mb[3]=m4.w!=0;
            }
            fi = ib[q]; ft = tb[q];
        }
        float vi[4] = {fi.x,fi.y,fi.z,fi.w};
        float vt[4] = {ft.x,ft.y,ft.z,ft.w};
#pragma unroll
        for (int e=0;e<4;e++){
            bool m = mb[e];
            unsigned k0 = fkey(vi[e]), k1 = fkey(vt[e]);
            bool cand0 = m && (k0>=klo0) && (k0<=khi0);
            bool cand1 = m && (k1>=klo1) && (k1<=khi1);
            if (m && k0<klo0){ clt0++; slt0+=vi[e]; } else if (m && k0>khi0){ cgt0++; sgt0+=vi[e]; }
            if (m && k1<klo1){ clt1++; slt1+=vt[e]; } else if (m && k1>khi1){ cgt1++; sgt1+=vt[e]; }
            unsigned bal = __ballot_sync(0xffffffffu, cand0);
            if (cand0) out0[wc0 + __popc(bal & lm)] = k0;
            wc0 += (unsigned)__popc(bal);
            bal = __ballot_sync(0xffffffffu, cand1);
            if (cand1) out1[wc1 + __popc(bal & lm)] = k1;
            wc1 += (unsigned)__popc(bal);
        }
    }
    if (lane==0){
        g_wcnt[0][b][blk*8+w] = wc0;
        g_wcnt[1][b][blk*8+w] = wc1;
    }
    unsigned r;
    r = bRSumU<8>(clt0, sh8u); if (tid==0 && r) atomicAdd(&g_cnt_lt[0][b], r);
    r = bRSumU<8>(cgt0, sh8u); if (tid==0 && r) atomicAdd(&g_cnt_gt[0][b], r);
    r = bRSumU<8>(clt1, sh8u); if (tid==0 && r) atomicAdd(&g_cnt_lt[1][b], r);
    r = bRSumU<8>(cgt1, sh8u); if (tid==0 && r) atomicAdd(&g_cnt_gt[1][b], r);
    float f;
    f = bRSumF<8>(slt0, sh8f); if (tid==0) atomicAdd(&g_sum_lt[0][b], (double)f);
    f = bRSumF<8>(sgt0, sh8f); if (tid==0) atomicAdd(&g_sum_gt[0][b], (double)f);
    f = bRSumF<8>(slt1, sh8f); if (tid==0) atomicAdd(&g_sum_lt[1][b], (double)f);
    f = bRSumF<8>(sgt1, sh8f); if (tid==0) atomicAdd(&g_sum_gt[1][b], (double)f);
}

// histogram select from global compact segments; exact fallback radix inlined
__global__ __launch_bounds__(256) void select_kernel(const float* inp, const float* tgt, const void* mask){
    int a = blockIdx.x, b = blockIdx.y, tid = threadIdx.x;
    int w = tid>>5, lane = tid&31;
    __shared__ unsigned swc[NSEGW];
    __shared__ unsigned hist[NBIN];
    __shared__ unsigned cand[1024];
    __shared__ unsigned s_cc, s_bin, s_bef, s_key;
    __shared__ unsigned sh8u[8];
    __shared__ double sh8d[8];
    for (int s=tid;s<NSEGW;s+=256) swc[s] = g_wcnt[a][b][s];
    for (int i=tid;i<NBIN;i+=256) hist[i]=0u;
    if (tid==0) s_cc=0u;
    __syncthreads();
    unsigned part=0;
    for (int s=tid;s<NSEGW;s+=256) part += swc[s];
    unsigned csize = bRSumU<8>(part, sh8u);
    unsigned cl = g_cnt_lt[a][b], cg = g_cnt_gt[a][b];
    unsigned n = cl + csize + cg;
    if (tid==0) g_ntot[a][b] = n;
    if (n==0u){
        if (tid==0){ g_med[a][b]=0.f; g_scale[a][b]=EPSV; }
        return;
    }
    unsigned k = (n-1u)>>1;
    bool fast = (k >= cl) && (k < cl+csize);
    if (fast){
        unsigned krem = k - cl;
        unsigned klo = g_klo[a][b], khi = g_khi[a][b];
        float scale = (float)NBIN / ((float)(khi - klo) + 1.0f);
        for (int s=w; s<NSEGW; s+=8){
            unsigned cnt = swc[s];
            const unsigned* G = &g_compact[a][b][(size_t)(s>>3)*CAPSEG + (s&7)*CAPW];
            for (unsigned i=lane; i<cnt; i+=32) atomicAdd(&hist[keybin(G[i], klo, scale)], 1u);
        }
        __syncthreads();
        {
            unsigned h[16], s=0;
#pragma unroll
            for (int j=0;j<16;j++){ h[j]=hist[tid*16+j]; s+=h[j]; }
            unsigned binc = bScanInc<8>(s, sh8u);
            unsigned bexc = binc - s;
            if (bexc<=krem && krem<binc){
                unsigned c=bexc;
#pragma unroll
                for (int j=0;j<16;j++){ if (krem < c+h[j]){ s_bin=tid*16+j; s_bef=c; break; } c+=h[j]; }
            }
        }
        __syncthreads();
        unsigned tbin = s_bin;
        for (int s=w; s<NSEGW; s+=8){
            unsigned cnt = swc[s];
            const unsigned* G = &g_compact[a][b][(size_t)(s>>3)*CAPSEG + (s&7)*CAPW];
            for (unsigned i=lane; i<cnt; i+=32){
                unsigned kk = G[i];
                if (keybin(kk, klo, scale)==tbin){ unsigned p=atomicAdd(&s_cc,1u); if (p<1024u) cand[p]=kk; }
            }
        }
        __syncthreads();
        unsigned cc = s_cc;
        if (cc <= 1024u){
            unsigned krem2 = krem - s_bef;
            for (unsigned j=tid;j<cc;j+=256){
                unsigned kj=cand[j]; unsigned less=0,eq=0;
                for (unsigned i2=0;i2<cc;i2++){ unsigned k2=cand[i2]; less += (k2<kj); eq += (k2==kj); }
                if (less<=krem2 && krem2<less+eq) s_key=kj;
            }
            __syncthreads();
            float m = fval(s_key);
            float lsf = 0.f;
            for (int s=w; s<NSEGW; s+=8){
                unsigned cnt = swc[s];
                const unsigned* G = &g_compact[a][b][(size_t)(s>>3)*CAPSEG + (s&7)*CAPW];
                for (unsigned i=lane; i<cnt; i+=32) lsf += fabsf(fval(G[i]) - m);
            }
            double ls = bRSumD<8>((double)lsf, sh8d);
            if (tid==0){
                double tot = (double)m*(double)cl - g_sum_lt[a][b]
                           + g_sum_gt[a][b] - (double)m*(double)cg + ls;
                g_med[a][b] = m;
                g_scale[a][b] = (float)fmax(tot/(double)n, (double)EPSV);
            }
            return;
        }
        __syncthreads();
    }
    // ---- inlined exact fallback: full 3-pass radix over this (a,b) row ----
    {
        int mode = g_mmode;
        const float* src = (a ? tgt : inp) + (size_t)b*HW;
        unsigned krem = k;
        unsigned pfx = 0u;
        __shared__ unsigned shbin, shbefore;
        for (int pass=0; pass<3; pass++){
            for (int i=tid;i<2048;i+=256) hist[i]=0u;
            __syncthreads();
            for (int i=tid;i<HW;i+=256){
                if (readmask(mask, (size_t)b*HW+i, mode)){
                    unsigned kk = fkey(src[i]);
                    bool f; unsigned bin;
                    if (pass==0){ f=true; bin=kk>>21; }
                    else if (pass==1){ f=((kk>>21)==pfx); bin=(kk>>10)&2047u; }
                    else { f=((kk>>10)==pfx); bin=kk&1023u; }
                    if (f) atomicAdd(&hist[bin], 1u);
                }
            }
            __syncthreads();
            unsigned h[8], s=0;
#pragma unroll
            for (int j=0;j<8;j++){ h[j]=hist[tid*8+j]; s+=h[j]; }
            unsigned inc = bScanInc<8>(s, sh8u);
            unsigned exc = inc - s;
            if (exc<=krem && krem<inc){
                unsigned c=exc; int bin=tid*8;
#pragma unroll
                for (int j=0;j<8;j++){ if (krem < c+h[j]){ bin=tid*8+j; break; } c+=h[j]; }
                shbin=(unsigned)bin; shbefore=c;
            }
            __syncthreads();
            if (pass==0) pfx = shbin;
            else if (pass==1) pfx = (pfx<<11)|shbin;
            else pfx = (pfx<<10)|shbin;
            krem -= shbefore;
            __syncthreads();
        }
        float m = fval(pfx);
        double ls=0.0;
        for (int i=tid;i<HW;i+=256){
            if (readmask(mask, (size_t)b*HW+i, mode)) ls += fabs((double)src[i]-(double)m);
        }
        ls = bRSumD<8>(ls, sh8d);
        if (tid==0){
            g_med[a][b] = m;
            g_scale[a][b] = (float)fmax(ls/(double)n, (double)EPSV);
        }
    }
}

__global__ __launch_bounds__(256) void gerr_kernel(const float* inp, const float* tgt, const void* mask){
    __shared__ float sh8[8];
    int b = blockIdx.y, tid = threadIdx.x;
    int mode = g_mmode;
    float m0=g_med[0][b], m1=g_med[1][b];
    float i0=1.f/g_scale[0][b], i1=1.f/g_scale[1][b];
    const float4* ib = (const float4*)(inp + (size_t)b*HW);
    const float4* tb = (const float4*)(tgt + (size_t)b*HW);
    int qchunk = HWQ/SEG;
    int qs = blockIdx.x*qchunk, qe = qs+qchunk;
    float acc=0.f;
    for (int q=qs+tid; q<qe; q+=256){
        size_t qi = (size_t)b*HWQ + q;
        bool mb[4];
        if (mode==0){
            uchar4 m4 = ((const uchar4*)mask)[qi];
            mb[0]=m4.x!=0; mb[1]=m4.y!=0; mb[2]=m4.z!=0; mb[3]=m4.w!=0;
        } else if (mode==1){
            float4 m4 = ((const float4*)mask)[qi];
            mb[0]=m4.x!=0.f; mb[1]=m4.y!=0.f; mb[2]=m4.z!=0.f; mb[3]=m4.w!=0.f;
        } else {
            int4 m4 = ((const int4*)mask)[qi];
            mb[0]=m4.x!=0; mb[1]=m4.y!=0; mb[2]=m4.z!=0; mb[3]=m4.w!=0;
        }
        float4 fi = ib[q], ft = tb[q];
        float vi[4]={fi.x,fi.y,fi.z,fi.w};
        float vt[4]={ft.x,ft.y,ft.z,ft.w};
#pragma unroll
        for (int e=0;e<4;e++){
            if (mb[e]){
                float gi = (vi[e]-m0)*i0;
                float gt = (vt[e]-m1)*i1;
                acc += fmaxf(fabsf(gi-gt), EPSV);
            }
        }
    }
    float r = bRSumF<8>(acc, sh8);
    if (threadIdx.x==0 && r!=0.f) atomicAdd(&g_gsum[b], r);
}

// ---------------- chain B ----------------
__device__ float edge_at(const float* img, const void* vmask, int b, int y, int x, int mode){
    if (y<3 || y>=HH-3 || x<3 || x>=WW-3) return 0.f;
    size_t vb = (size_t)b*HW;
    bool ok = true;
#pragma unroll
    for (int dy=-1;dy<=1;dy++)
#pragma unroll
        for (int dx=-1;dx<=1;dx++)
            ok &= readmask(vmask, vb + (size_t)(y+dy)*WW + (x+dx), mode);
    float sgx=0.f, sgy=0.f;
#pragma unroll
    for (int c=0;c<3;c++){
        const float* p = img + ((size_t)b*3 + c)*HW;
        float a00=p[(y-1)*WW+x-1], a01=p[(y-1)*WW+x], a02=p[(y-1)*WW+x+1];
        float a10=p[y*WW+x-1],                         a12=p[y*WW+x+1];
        float a20=p[(y+1)*WW+x-1], a21=p[(y+1)*WW+x], a22=p[(y+1)*WW+x+1];
        float gx = (a02 - a00) + 2.f*(a12 - a10) + (a22 - a20);
        float gy = (a20 - a00) + 2.f*(a21 - a01) + (a22 - a02);
        gx *= 0.125f; gy *= 0.125f;
        sgx += gx*gx; sgy += gy*gy;
    }
    float gxr = sqrtf(sgx/3.f);
    float gyr = sqrtf(sgy/3.f);
    return ok ? sqrtf(gxr*gxr + gyr*gyr) : 0.f;
}

__global__ __launch_bounds__(1024) void edge_topk_kernel(const float* image, const void* vmask){
    __shared__ unsigned long long key[2048];
    __shared__ unsigned shm[32];
    int b = blockIdx.x, tid = threadIdx.x;
    int mode = detect_mode<32>(vmask, shm);
    if (tid==0){ g_epsum[b]=0.f; g_epcnt[b]=0u; }
    for (int j=tid;j<2048;j+=1024){
        unsigned long long kv = 0ull;
        if (j < NC){
            int oy = j/OW, ox = j%OW;
            float sy = (float)(480.0/34.0);
            float sx = (float)(640.0/45.0);
            float cyf = fminf(fmaxf(((float)oy + 0.5f)*sy - 0.5f, 0.f), (float)(HH-1));
            float cxf = fminf(fmaxf(((float)ox + 0.5f)*sx - 0.5f, 0.f), (float)(WW-1));
            int y0 = (int)floorf(cyf); int y1 = min(y0+1, HH-1); float wy = cyf - (float)y0;
            int x0 = (int)floorf(cxf); int x1 = min(x0+1, WW-1); float wx = cxf - (float)x0;
            float e00 = edge_at(image, vmask, b, y0, x0, mode);
            float e01 = edge_at(image, vmask, b, y0, x1, mode);
            float e10 = edge_at(image, vmask, b, y1, x0, mode);
            float e11 = edge_at(image, vmask, b, y1, x1, mode);
            float val = ((e00*(1.f-wy))*(1.f-wx)) + ((e01*(1.f-wy))*wx)
                      + ((e10*wy)*(1.f-wx)) + ((e11*wy)*wx);
            kv = ((unsigned long long)fkey(val) << 32) | (unsigned)(0xFFFFFFFFu - (unsigned)j);
        }
        key[j] = kv;
    }
    __syncthreads();
    for (int size=2; size<=2048; size<<=1){
        for (int stride=size>>1; stride>0; stride>>=1){
            for (int e=tid; e<2048; e+=1024){
                int p = e ^ stride;
                if (p > e){
                    bool up = (e & size)==0;
                    unsigned long long A = key[e], Bk = key[p];
                    bool sw = up ? (A < Bk) : (A > Bk);
                    if (sw){ key[e]=Bk; key[p]=A; }
                }
            }
            __syncthreads();
        }
    }
    if (tid < K_TOP){
        unsigned idx = 0xFFFFFFFFu - (unsigned)(key[tid] & 0xFFFFFFFFull);
        g_cy[b][tid] = (int)(idx/OW)*14;
        g_cx[b][tid] = (int)(idx%OW)*14;
    }
}

__global__ __launch_bounds__(256) void patch_kernel(const float* inp, const float* tgt, const void* mask){
    __shared__ unsigned shm[8];
    int mode = detect_mode<8>(mask, shm);
    int b = blockIdx.y, w = threadIdx.x>>5, lane = threadIdx.x&31;
    int p = blockIdx.x*8 + w;
    if (p >= K_TOP) return;
    int cy = g_cy[b][p], cx = g_cx[b][p];
    unsigned ki[20], kt[20];
    unsigned mmb = 0;
    unsigned lc = 0;
#pragma unroll
    for (int s=0;s<20;s++){
        int i = s*32 + lane;
        float vi=0.f, vt=0.f;
        bool m = false;
        if (i < PS){
            int dy = i/KS - 12, dx = i%KS - 12;
            int y = cy+dy, x = cx+dx;
            if (y>=0 && y<HH && x>=0 && x<WW){
                size_t idx = (size_t)b*HW + (size_t)y*WW + x;
                m = readmask(mask, idx, mode);
                vi = inp[idx];
                vt = tgt[idx];
            }
        }
        if (m){ mmb |= (1u<<s); lc++; } else { vi=0.f; vt=0.f; }
        ki[s] = fkey(vi); kt[s] = fkey(vt);
    }
    unsigned n = __reduce_add_sync(0xffffffffu, lc);

    float med0=0.f, med1=0.f;
    if (n){
        unsigned k = (n-1u)>>1;
        unsigned lo0=0u, hi0=0xFFFFFFFFu, lo1=0u, hi1=0xFFFFFFFFu;
        while (lo0 < hi0 || lo1 < hi1){
            unsigned mid0 = lo0 + ((hi0-lo0)>>1);
            unsigned mid1 = lo1 + ((hi1-lo1)>>1);
            unsigned c=0;
#pragma unroll
            for (int s=0;s<20;s++){
                if ((mmb>>s)&1u){
                    c += (ki[s] <= mid0) ? 1u : 0u;
                    c += (kt[s] <= mid1) ? 0x10000u : 0u;
                }
            }
            c = __reduce_add_sync(0xffffffffu, c);
            unsigned c0 = c & 0xFFFFu, c1 = c >> 16;
            if (lo0 < hi0){ if (c0 >= k+1u) hi0=mid0; else lo0=mid0+1u; }
            if (lo1 < hi1){ if (c1 >= k+1u) hi1=mid1; else lo1=mid1+1u; }
        }
        med0 = fval(hi0);
        med1 = fval(hi1);
    }

    float a0=0.f, a1=0.f;
#pragma unroll
    for (int s=0;s<20;s++){
        if ((mmb>>s)&1u){
            a0 += fabsf(fval(ki[s])-med0);
            a1 += fabsf(fval(kt[s])-med1);
        }
    }
    a0 = wRSumF(a0); a1 = wRSumF(a1);
    float fn = fmaxf((float)n, 1.f);
    float d0 = fmaxf(a0/fn, EPSV);
    float d1 = fmaxf(a1/fn, EPSV);
    float r0 = 1.f/d0, r1 = 1.f/d1;

    float e = 0.f;
#pragma unroll
    for (int s=0;s<20;s++){
        if ((mmb>>s)&1u){
            float gi = (fval(ki[s])-med0)*r0;
            float gt = (fval(kt[s])-med1)*r1;
            e += fmaxf(fabsf(gi-gt), EPSV);
        }
    }
    e = wRSumF(e);
    if (lane==0 && n>=4u){
        float ep = sqrtf(fmaxf(e/fn, EPSV));
        atomicAdd(&g_epsum[b], ep);
        atomicAdd(&g_epcnt[b], 1u);
    }
}

__global__ void final_kernel(float* out){
    int b = threadIdx.x;
    if (b >= BB) return;
    float ep = g_epsum[b] / fmaxf((float)g_epcnt[b], 1.f);
    float fn = fmaxf((float)g_ntot[0][b], 1.f);
    float eg = sqrtf(fmaxf(g_gsum[b]/fn, EPSV));
    out[b] = 0.5f*(ep + eg);
}

// ---------------- launch ----------------
extern "C" void kernel_launch(void* const* d_in, const int* in_sizes, int n_in,
                              void* d_out, int out_size) {
    const float* inp  = (const float*)d_in[0];
    const float* tgt  = (const float*)d_in[1];
    const void*  mask = d_in[2];
    const float* img  = (const float*)d_in[3];
    const void*  vmsk = d_in[4];
    float* out = (float*)d_out;

    static bool once = false;
    static cudaStream_t s2;
    static cudaEvent_t evFork, evJoin;
    if (!once){
        cudaFuncSetAttribute(sample_kernel, cudaFuncAttributeMaxDynamicSharedMemorySize, SAMP*4);
        cudaStreamCreateWithFlags(&s2, cudaStreamNonBlocking);
        cudaEventCreateWithFlags(&evFork, cudaEventDisableTiming);
        cudaEventCreateWithFlags(&evJoin, cudaEventDisableTiming);
        once = true;
    }

    // fork chain B at graph root (fully independent of chain A)
    cudaEventRecord(evFork, 0);
    cudaStreamWaitEvent(s2, evFork, 0);
    edge_topk_kernel<<<BB,1024,0,s2>>>(img, vmsk);
    patch_kernel<<<dim3((K_TOP+7)/8,BB),256,0,s2>>>(inp, tgt, mask);
    cudaEventRecord(evJoin, s2);

    // chain A on default stream
    sample_kernel<<<dim3(2,BB),256,SAMP*4>>>(inp, tgt, mask);
    passA_kernel<<<dim3(SEG,BB),256>>>(inp, tgt, mask);
    select_kernel<<<dim3(2,BB),256>>>(inp, tgt, mask);
    gerr_kernel<<<dim3(SEG,BB),256>>>(inp, tgt, mask);

    // join and finalize
    cudaStreamWaitEvent(0, evJoin, 0);
    final_kernel<<<1,32>>>(out);
}

// round 17
// speedup vs baseline: 1.3375x; 1.3375x over previous
#include <cuda_runtime.h>
#include <cuda_bf16.h>
#include <math.h>

#define BB 32
#define HH 480
#define WW 640
#define HW (HH*WW)
#define HWQ (HW/4)
#define OH 34
#define OW 45
#define NC (OH*OW)      // 1530
#define K_TOP 153
#define KS 25
#define PS (KS*KS)      // 625
#define EPSV 1e-5f
#define SEG 40
#define CAPSEG (HW/SEG)     // 7680 elems per passA block region
#define CAPW (CAPSEG/8)     // 960 per warp
#define NSEGW (SEG*8)       // 320 warp segments per (a,b)
#define SAMP 16384
#define NCLUS 1024
#define CSTRIDE (HW/NCLUS)  // 300 floats between cluster starts (1200B, 16B aligned)
#define NBIN 4096

// ---------------- device scratch ----------------
__device__ unsigned g_klo[2][BB], g_khi[2][BB];
__device__ unsigned g_cnt_lt[2][BB], g_cnt_gt[2][BB];
__device__ double   g_sum_lt[2][BB], g_sum_gt[2][BB];
__device__ unsigned g_wcnt[2][BB][NSEGW];
__device__ unsigned g_compact[2][BB][HW];
__device__ float    g_med[2][BB], g_scale[2][BB];
__device__ unsigned g_ntot[2][BB];
__device__ int      g_fb[2][BB];
__device__ float    g_gsum[BB], g_epsum[BB];
__device__ unsigned g_epcnt[BB];
__device__ int      g_mmode;   // published by sample(0,0); chain-A consumers only
__device__ int      g_cy[BB][K_TOP], g_cx[BB][K_TOP];

// ---------------- helpers ----------------
__device__ __forceinline__ unsigned fkey(float v){
    unsigned u = __float_as_uint(v);
    return (u & 0x80000000u) ? ~u : (u | 0x80000000u);
}
__device__ __forceinline__ float fval(unsigned u){
    unsigned o = (u & 0x80000000u) ? (u & 0x7fffffffu) : ~u;
    return __uint_as_float(o);
}
__device__ __forceinline__ bool readmask(const void* p, size_t i, int mode){
    if (mode == 0) return ((const unsigned char*)p)[i] != 0;
    if (mode == 1) return ((const float*)p)[i] != 0.0f;
    return ((const int*)p)[i] != 0;
}
// monotone binning: key in [klo, khi] -> bin in [0, NBIN)
__device__ __forceinline__ unsigned keybin(unsigned key, unsigned klo, float scale){
    return min((unsigned)(NBIN-1), (unsigned)((float)(key - klo) * scale));
}

template<int NW>
__device__ __forceinline__ float bRSumF(float v, float* sh){
    int lane = threadIdx.x & 31, w = threadIdx.x >> 5;
#pragma unroll
    for (int o=16;o>0;o>>=1) v += __shfl_down_sync(0xffffffffu, v, o);
    if (lane==0) sh[w]=v;
    __syncthreads();
    if (w==0){
        float r = (lane<NW)? sh[lane]:0.f;
#pragma unroll
        for (int o=NW>>1;o>0;o>>=1) r += __shfl_down_sync(0xffffffffu, r, o);
        if (lane==0) sh[0]=r;
    }
    __syncthreads();
    float r = sh[0];
    __syncthreads();
    return r;
}
template<int NW>
__device__ __forceinline__ unsigned bRSumU(unsigned v, unsigned* sh){
    int lane = threadIdx.x & 31, w = threadIdx.x >> 5;
#pragma unroll
    for (int o=16;o>0;o>>=1) v += __shfl_down_sync(0xffffffffu, v, o);
    if (lane==0) sh[w]=v;
    __syncthreads();
    if (w==0){
        unsigned r = (lane<NW)? sh[lane]:0u;
#pragma unroll
        for (int o=NW>>1;o>0;o>>=1) r += __shfl_down_sync(0xffffffffu, r, o);
        if (lane==0) sh[0]=r;
    }
    __syncthreads();
    unsigned r = sh[0];
    __syncthreads();
    return r;
}
template<int NW>
__device__ __forceinline__ unsigned bRMinU(unsigned v, unsigned* sh){
    int lane = threadIdx.x & 31, w = threadIdx.x >> 5;
#pragma unroll
    for (int o=16;o>0;o>>=1) v = min(v, __shfl_down_sync(0xffffffffu, v, o));
    if (lane==0) sh[w]=v;
    __syncthreads();
    if (w==0){
        unsigned r = (lane<NW)? sh[lane]:0xFFFFFFFFu;
#pragma unroll
        for (int o=NW>>1;o>0;o>>=1) r = min(r, __shfl_down_sync(0xffffffffu, r, o));
        if (lane==0) sh[0]=r;
    }
    __syncthreads();
    unsigned r = sh[0];
    __syncthreads();
    return r;
}
template<int NW>
__device__ __forceinline__ unsigned bRMaxU(unsigned v, unsigned* sh){
    int lane = threadIdx.x & 31, w = threadIdx.x >> 5;
#pragma unroll
    for (int o=16;o>0;o>>=1) v = max(v, __shfl_down_sync(0xffffffffu, v, o));
    if (lane==0) sh[w]=v;
    __syncthreads();
    if (w==0){
        unsigned r = (lane<NW)? sh[lane]:0u;
#pragma unroll
        for (int o=NW>>1;o>0;o>>=1) r = max(r, __shfl_down_sync(0xffffffffu, r, o));
        if (lane==0) sh[0]=r;
    }
    __syncthreads();
    unsigned r = sh[0];
    __syncthreads();
    return r;
}
template<int NW>
__device__ __forceinline__ double bRSumD(double v, double* sh){
    int lane = threadIdx.x & 31, w = threadIdx.x >> 5;
#pragma unroll
    for (int o=16;o>0;o>>=1) v += __shfl_down_sync(0xffffffffu, v, o);
    if (lane==0) sh[w]=v;
    __syncthreads();
    if (w==0){
        double r = (lane<NW)? sh[lane]:0.0;
#pragma unroll
        for (int o=NW>>1;o>0;o>>=1) r += __shfl_down_sync(0xffffffffu, r, o);
        if (lane==0) sh[0]=r;
    }
    __syncthreads();
    double r = sh[0];
    __syncthreads();
    return r;
}
// inclusive scan over 256 thread values
__device__ __forceinline__ unsigned bScanInc256(unsigned v, unsigned* sh){
    int lane = threadIdx.x & 31, w = threadIdx.x >> 5;
    unsigned x = v;
#pragma unroll
    for (int o=1;o<32;o<<=1){ unsigned t=__shfl_up_sync(0xffffffffu,x,o); if(lane>=o) x+=t; }
    if (lane==31) sh[w]=x;
    __syncthreads();
    if (w==0){
        unsigned y = (lane<8)? sh[lane]:0u;
#pragma unroll
        for (int o=1;o<8;o<<=1){ unsigned t=__shfl_up_sync(0xffffffffu,y,o); if(lane>=o) y+=t; }
        if (lane<8) sh[lane]=y;
    }
    __syncthreads();
    unsigned off = (w>0)? sh[w-1]:0u;
    unsigned r = x + off;
    __syncthreads();
    return r;
}
__device__ __forceinline__ float wRSumF(float v){
#pragma unroll
    for (int o=16;o>0;o>>=1) v += __shfl_xor_sync(0xffffffffu, v, o);
    return v;
}
// block-local mode detect from first 4096 mask bytes (L2-resident)
template<int NW>
__device__ __forceinline__ int detect_mode(const void* mask, unsigned* sh){
    const unsigned char* m = (const unsigned char*)mask;
    unsigned c=0;
    for (int i=threadIdx.x;i<4096;i+=NW*32) c += (m[i]!=0);
    c = bRSumU<NW>(c, sh);
    return (c>2765)?0 : ((c>1382)?1:2);
}

extern __shared__ unsigned sL[];

// ---------------- kernels ----------------
// clustered sampling with batched independent loads; bracket = histogram bin edges
__global__ __launch_bounds__(256) void sample_kernel(const float* inp, const float* tgt, const void* mask){
    int a = blockIdx.x, b = blockIdx.y, tid = threadIdx.x;
    __shared__ unsigned hist[NBIN];
    __shared__ unsigned sh8[8];
    __shared__ unsigned s_bin0, s_bin1;
    int mode = detect_mode<8>(mask, sh8);
    if (tid==0){
        if (a==0 && b==0) g_mmode = mode;   // chain A consumers run after sample
        g_cnt_lt[a][b]=0u; g_cnt_gt[a][b]=0u;
        g_sum_lt[a][b]=0.0; g_sum_gt[a][b]=0.0; g_fb[a][b]=0;
        if (a==0) g_gsum[b]=0.f;
    }
    const float* src = (a ? tgt : inp) + (size_t)b*HW;
    unsigned lc=0, lmin=0xFFFFFFFFu, lmax=0u;
    // each thread owns whole clusters of 16 contiguous floats; all loads independent
    for (int c=tid; c<NCLUS; c+=256){
        int base = c*CSTRIDE;                  // 1200B stride, 16B aligned
        const float4* vp = (const float4*)(src + base);
        float4 v4[4];
#pragma unroll
        for (int q=0;q<4;q++) v4[q] = vp[q];   // unconditional, independent
        bool mb[16];
        size_t mbase = (size_t)b*HW + base;
        if (mode==0){
            const uchar4* mp = (const uchar4*)((const unsigned char*)mask + mbase);
#pragma unroll
            for (int q=0;q<4;q++){ uchar4 m4=mp[q]; mb[q*4]=m4.x!=0; mb[q*4+1]=m4.y!=0; mb[q*4+2]=m4.z!=0; mb[q*4+3]=m4.w!=0; }
        } else if (mode==1){
            const float4* mp = (const float4*)((const float*)mask + mbase);
#pragma unroll
            for (int q=0;q<4;q++){ float4 m4=mp[q]; mb[q*4]=m4.x!=0.f; mb[q*4+1]=m4.y!=0.f; mb[q*4+2]=m4.z!=0.f; mb[q*4+3]=m4.w!=0.f; }
        } else {
            const int4* mp = (const int4*)((const int*)mask + mbase);
#pragma unroll
            for (int q=0;q<4;q++){ int4 m4=mp[q]; mb[q*4]=m4.x!=0; mb[q*4+1]=m4.y!=0; mb[q*4+2]=m4.z!=0; mb[q*4+3]=m4.w!=0; }
        }
        const float* vf = (const float*)v4;
#pragma unroll
        for (int j=0;j<16;j++){
            unsigned key = 0xFFFFFFFFu;
            if (mb[j]){
                key = fkey(vf[j]); lc++;
                lmin = min(lmin, key); lmax = max(lmax, key);
            }
            sL[c*16 + j] = key;
        }
    }
    for (int i=tid;i<NBIN;i+=256) hist[i]=0u;
    __syncthreads();
    unsigned ms = bRSumU<8>(lc, sh8);
    if (ms==0u){
        if (tid==0){ g_klo[a][b]=0u; g_khi[a][b]=0xFFFFFFFFu; }
        return;
    }
    unsigned kmin = bRMinU<8>(lmin, sh8);
    unsigned kmax = bRMaxU<8>(lmax, sh8);
    float scale = (float)NBIN / ((float)(kmax - kmin) + 1.0f);
    unsigned rlo = (unsigned)(0.47f*(float)ms);
    unsigned rhi = (unsigned)(0.53f*(float)ms);
    if (rhi >= ms) rhi = ms-1u;
    for (int i=tid;i<SAMP;i+=256){
        unsigned kk = sL[i];
        if (kk != 0xFFFFFFFFu) atomicAdd(&hist[keybin(kk, kmin, scale)], 1u);
    }
    __syncthreads();
    // scan 4096 bins, find bins containing ranks rlo, rhi
    {
        unsigned h[16], s=0;
#pragma unroll
        for (int j=0;j<16;j++){ h[j]=hist[tid*16+j]; s+=h[j]; }
        unsigned inc = bScanInc256(s, sh8);
        unsigned exc = inc - s;
        if (exc<=rlo && rlo<inc){
            unsigned c=exc;
#pragma unroll
            for (int j=0;j<16;j++){ if (rlo < c+h[j]){ s_bin0=tid*16+j; break; } c+=h[j]; }
        }
        if (exc<=rhi && rhi<inc){
            unsigned c=exc;
#pragma unroll
            for (int j=0;j<16;j++){ if (rhi < c+h[j]){ s_bin1=tid*16+j; break; } c+=h[j]; }
        }
    }
    __syncthreads();
    if (tid==0){
        // bracket = bin edges (widened outward); thresholds need not be data keys
        double inv = 1.0 / (double)scale;
        unsigned long long lo64 = (unsigned long long)kmin
                                + (unsigned long long)floor((double)s_bin0 * inv);
        unsigned long long hi64 = (unsigned long long)kmin
                                + (unsigned long long)ceil((double)(s_bin1 + 1u) * inv);
        g_klo[a][b] = (lo64 > 0xFFFFFFFFull) ? 0xFFFFFFFFu : (unsigned)lo64;
        g_khi[a][b] = (hi64 > 0xFFFFFFFFull) ? 0xFFFFFFFFu : (unsigned)hi64;
    }
}

// one pass: counts/sums outside bracket, atomic-free segmented compaction inside
__global__ __launch_bounds__(256) void passA_kernel(const float* inp, const float* tgt, const void* mask){
    int b = blockIdx.y, blk = blockIdx.x, tid = threadIdx.x;
    int lane = tid & 31, w = tid >> 5;
    int mode = g_mmode;
    unsigned klo0=g_klo[0][b], khi0=g_khi[0][b], klo1=g_klo[1][b], khi1=g_khi[1][b];
    __shared__ unsigned sh8u[8];
    __shared__ float sh8f[8];
    const float4* ib = (const float4*)(inp + (size_t)b*HW);
    const float4* tb = (const float4*)(tgt + (size_t)b*HW);
    const int QW = HWQ/SEG/8;        // 240 float4 per warp
    int qw0 = blk*(HWQ/SEG) + w*QW;
    unsigned* out0 = &g_compact[0][b][(size_t)blk*CAPSEG + w*CAPW];
    unsigned* out1 = &g_compact[1][b][(size_t)blk*CAPSEG + w*CAPW];
    unsigned wc0=0, wc1=0;
    unsigned clt0=0,cgt0=0,clt1=0,cgt1=0;
    float slt0=0.f,sgt0=0.f,slt1=0.f,sgt1=0.f;
    unsigned lm = (1u<<lane)-1u;
    const int ITER = (QW + 31)/32;   // 8
    for (int it=0; it<ITER; it++){
        int qo = it*32 + lane;
        bool valid = (qo < QW);
        int q = qw0 + qo;
        float4 fi = {0.f,0.f,0.f,0.f}, ft = {0.f,0.f,0.f,0.f};
        bool mb[4] = {false,false,false,false};
        if (valid){
            size_t qi = (size_t)b*HWQ + q;
            if (mode==0){
                uchar4 m4 = ((const uchar4*)mask)[qi];
                mb[0]=m4.x!=0; mb[1]=m4.y!=0; mb[2]=m4.z!=0; mb[3]=m4.w!=0;
            } else if (mode==1){
                float4 m4 = ((const float4*)mask)[qi];
                mb[0]=m4.x!=0.f; mb[1]=m4.y!=0.f; mb[2]=m4.z!=0.f; mb[3]=m4.w!=0.f;
            } else {
                int4 m4 = ((const int4*)mask)[qi];
                mb[0]=m4.x!=0; mb[1]=m4.y!=0; mb[2]=m4.z!=0; mb[3]=m4.w!=0;
            }
            fi = ib[q]; ft = tb[q];
        }
        float vi[4] = {fi.x,fi.y,fi.z,fi.w};
        float vt[4] = {ft.x,ft.y,ft.z,ft.w};
#pragma unroll
        for (int e=0;e<4;e++){
            bool m = mb[e];
            unsigned k0 = fkey(vi[e]), k1 = fkey(vt[e]);
            bool cand0 = m && (k0>=klo0) && (k0<=khi0);
            bool cand1 = m && (k1>=klo1) && (k1<=khi1);
            if (m && k0<klo0){ clt0++; slt0+=vi[e]; } else if (m && k0>khi0){ cgt0++; sgt0+=vi[e]; }
            if (m && k1<klo1){ clt1++; slt1+=vt[e]; } else if (m && k1>khi1){ cgt1++; sgt1+=vt[e]; }
            unsigned bal = __ballot_sync(0xffffffffu, cand0);
            if (cand0) out0[wc0 + __popc(bal & lm)] = k0;
            wc0 += (unsigned)__popc(bal);
            bal = __ballot_sync(0xffffffffu, cand1);
            if (cand1) out1[wc1 + __popc(bal & lm)] = k1;
            wc1 += (unsigned)__popc(bal);
        }
    }
    if (lane==0){
        g_wcnt[0][b][blk*8+w] = wc0;
        g_wcnt[1][b][blk*8+w] = wc1;
    }
    unsigned r;
    r = bRSumU<8>(clt0, sh8u); if (tid==0 && r) atomicAdd(&g_cnt_lt[0][b], r);
    r = bRSumU<8>(cgt0, sh8u); if (tid==0 && r) atomicAdd(&g_cnt_gt[0][b], r);
    r = bRSumU<8>(clt1, sh8u); if (tid==0 && r) atomicAdd(&g_cnt_lt[1][b], r);
    r = bRSumU<8>(cgt1, sh8u); if (tid==0 && r) atomicAdd(&g_cnt_gt[1][b], r);
    float f;
    f = bRSumF<8>(slt0, sh8f); if (tid==0) atomicAdd(&g_sum_lt[0][b], (double)f);
    f = bRSumF<8>(sgt0, sh8f); if (tid==0) atomicAdd(&g_sum_gt[0][b], (double)f);
    f = bRSumF<8>(slt1, sh8f); if (tid==0) atomicAdd(&g_sum_lt[1][b], (double)f);
    f = bRSumF<8>(sgt1, sh8f); if (tid==0) atomicAdd(&g_sum_gt[1][b], (double)f);
}

// histogram select straight from global compact segments (no shared staging)
__global__ __launch_bounds__(256) void select_kernel(){
    int a = blockIdx.x, b = blockIdx.y, tid = threadIdx.x;
    int w = tid>>5, lane = tid&31;
    __shared__ unsigned swc[NSEGW];
    __shared__ unsigned hist[NBIN];
    __shared__ unsigned cand[1024];
    __shared__ unsigned s_cc, s_bin, s_bef, s_key;
    __shared__ unsigned sh8u[8];
    __shared__ double sh8d[8];
    for (int s=tid;s<NSEGW;s+=256) swc[s] = g_wcnt[a][b][s];
    for (int i=tid;i<NBIN;i+=256) hist[i]=0u;
    if (tid==0) s_cc=0u;
    __syncthreads();
    unsigned part=0;
    for (int s=tid;s<NSEGW;s+=256) part += swc[s];
    unsigned csize = bRSumU<8>(part, sh8u);
    unsigned cl = g_cnt_lt[a][b], cg = g_cnt_gt[a][b];
    unsigned n = cl + csize + cg;
    if (tid==0) g_ntot[a][b] = n;
    if (n==0u){
        if (tid==0){ g_med[a][b]=0.f; g_scale[a][b]=EPSV; g_fb[a][b]=0; }
        return;
    }
    unsigned k = (n-1u)>>1;
    if (k < cl || k >= cl+csize){
        if (tid==0) g_fb[a][b]=1;
        return;
    }
    unsigned krem = k - cl;
    unsigned klo = g_klo[a][b], khi = g_khi[a][b];
    float scale = (float)NBIN / ((float)(khi - klo) + 1.0f);
    // 1) histogram sweep over global segments
    for (int s=w; s<NSEGW; s+=8){
        unsigned cnt = swc[s];
        const unsigned* G = &g_compact[a][b][(size_t)(s>>3)*CAPSEG + (s&7)*CAPW];
        for (unsigned i=lane; i<cnt; i+=32) atomicAdd(&hist[keybin(G[i], klo, scale)], 1u);
    }
    __syncthreads();
    // 2) scan bins to locate rank's bin
    {
        unsigned h[16], s=0;
#pragma unroll
        for (int j=0;j<16;j++){ h[j]=hist[tid*16+j]; s+=h[j]; }
        unsigned binc = bScanInc256(s, sh8u);
        unsigned bexc = binc - s;
        if (bexc<=krem && krem<binc){
            unsigned c=bexc;
#pragma unroll
            for (int j=0;j<16;j++){ if (krem < c+h[j]){ s_bin=tid*16+j; s_bef=c; break; } c+=h[j]; }
        }
    }
    __syncthreads();
    unsigned tbin = s_bin;
    // 3) collect the target bin's keys (L2-hit re-read)
    for (int s=w; s<NSEGW; s+=8){
        unsigned cnt = swc[s];
        const unsigned* G = &g_compact[a][b][(size_t)(s>>3)*CAPSEG + (s&7)*CAPW];
        for (unsigned i=lane; i<cnt; i+=32){
            unsigned kk = G[i];
            if (keybin(kk, klo, scale)==tbin){ unsigned p=atomicAdd(&s_cc,1u); if (p<1024u) cand[p]=kk; }
        }
    }
    __syncthreads();
    unsigned cc = s_cc;
    if (cc > 1024u){
        if (tid==0) g_fb[a][b]=1;
        return;
    }
    unsigned krem2 = krem - s_bef;
    for (unsigned j=tid;j<cc;j+=256){
        unsigned kj=cand[j]; unsigned less=0,eq=0;
        for (unsigned i2=0;i2<cc;i2++){ unsigned k2=cand[i2]; less += (k2<kj); eq += (k2==kj); }
        if (less<=krem2 && krem2<less+eq) s_key=kj;
    }
    __syncthreads();
    float m = fval(s_key);
    // 4) abs-sum sweep (L2-hit re-read)
    float lsf = 0.f;
    for (int s=w; s<NSEGW; s+=8){
        unsigned cnt = swc[s];
        const unsigned* G = &g_compact[a][b][(size_t)(s>>3)*CAPSEG + (s&7)*CAPW];
        for (unsigned i=lane; i<cnt; i+=32) lsf += fabsf(fval(G[i]) - m);
    }
    double ls = bRSumD<8>((double)lsf, sh8d);
    if (tid==0){
        double tot = (double)m*(double)cl - g_sum_lt[a][b]
                   + g_sum_gt[a][b] - (double)m*(double)cg + ls;
        double sc = tot / (double)n;
        g_med[a][b] = m;
        g_scale[a][b] = (float)fmax(sc, (double)EPSV);
        g_fb[a][b]=0;
    }
}

// exact full recompute — only if bracket failed
__global__ __launch_bounds__(256) void fallback_kernel(const float* inp, const float* tgt, const void* mask){
    int a = blockIdx.x, b = blockIdx.y, tid = threadIdx.x;
    if (!g_fb[a][b]) return;
    __shared__ unsigned sh[2048];
    __shared__ unsigned sh8u[8];
    __shared__ double sh8d[8];
    __shared__ unsigned shbin, shbefore;
    int mode = g_mmode;
    const float* src = (a ? tgt : inp) + (size_t)b*HW;
    unsigned n = g_ntot[a][b];
    unsigned krem = (n-1u)>>1;
    unsigned pfx = 0u;
    for (int pass=0; pass<3; pass++){
        for (int i=tid;i<2048;i+=256) sh[i]=0u;
        __syncthreads();
        for (int i=tid;i<HW;i+=256){
            if (readmask(mask, (size_t)b*HW+i, mode)){
                unsigned kk = fkey(src[i]);
                bool f; unsigned bin;
                if (pass==0){ f=true; bin=kk>>21; }
                else if (pass==1){ f=((kk>>21)==pfx); bin=(kk>>10)&2047u; }
                else { f=((kk>>10)==pfx); bin=kk&1023u; }
                if (f) atomicAdd(&sh[bin], 1u);
            }
        }
        __syncthreads();
        unsigned h[8], s=0;
#pragma unroll
        for (int j=0;j<8;j++){ h[j]=sh[tid*8+j]; s+=h[j]; }
        unsigned inc = bScanInc256(s, sh8u);
        unsigned exc = inc - s;
        if (exc<=krem && krem<inc){
            unsigned c=exc; int bin=tid*8;
#pragma unroll
            for (int j=0;j<8;j++){ if (krem < c+h[j]){ bin=tid*8+j; break; } c+=h[j]; }
            shbin=(unsigned)bin; shbefore=c;
        }
        __syncthreads();
        if (pass==0) pfx = shbin;
        else if (pass==1) pfx = (pfx<<11)|shbin;
        else pfx = (pfx<<10)|shbin;
        krem -= shbefore;
        __syncthreads();
    }
    float m = fval(pfx);
    double ls=0.0;
    for (int i=tid;i<HW;i+=256){
        if (readmask(mask, (size_t)b*HW+i, mode)) ls += fabs((double)src[i]-(double)m);
    }
    ls = bRSumD<8>(ls, sh8d);
    if (tid==0){
        g_med[a][b] = m;
        g_scale[a][b] = (float)fmax(ls/(double)n, (double)EPSV);
    }
}

__global__ __launch_bounds__(256) void gerr_kernel(const float* inp, const float* tgt, const void* mask){
    __shared__ float sh8[8];
    int b = blockIdx.y, tid = threadIdx.x;
    int mode = g_mmode;
    float m0=g_med[0][b], m1=g_med[1][b];
    float i0=1.f/g_scale[0][b], i1=1.f/g_scale[1][b];
    const float4* ib = (const float4*)(inp + (size_t)b*HW);
    const float4* tb = (const float4*)(tgt + (size_t)b*HW);
    int qchunk = HWQ/SEG;
    int qs = blockIdx.x*qchunk, qe = qs+qchunk;
    float acc=0.f;
    for (int q=qs+tid; q<qe; q+=256){
        size_t qi = (size_t)b*HWQ + q;
        bool mb[4];
        if (mode==0){
            uchar4 m4 = ((const uchar4*)mask)[qi];
            mb[0]=m4.x!=0; mb[1]=m4.y!=0; mb[2]=m4.z!=0; mb[3]=m4.w!=0;
        } else if (mode==1){
            float4 m4 = ((const float4*)mask)[qi];
            mb[0]=m4.x!=0.f; mb[1]=m4.y!=0.f; mb[2]=m4.z!=0.f; mb[3]=m4.w!=0.f;
        } else {
            int4 m4 = ((const int4*)mask)[qi];
            mb[0]=m4.x!=0; mb[1]=m4.y!=0; mb[2]=m4.z!=0; mb[3]=m4.w!=0;
        }
        float4 fi = ib[q], ft = tb[q];
        float vi[4]={fi.x,fi.y,fi.z,fi.w};
        float vt[4]={ft.x,ft.y,ft.z,ft.w};
#pragma unroll
        for (int e=0;e<4;e++){
            if (mb[e]){
                float gi = (vi[e]-m0)*i0;
                float gt = (vt[e]-m1)*i1;
                acc += fmaxf(fabsf(gi-gt), EPSV);
            }
        }
    }
    float r = bRSumF<8>(acc, sh8);
    if (threadIdx.x==0 && r!=0.f) atomicAdd(&g_gsum[b], r);
}

// edge value with fully independent loads (no short-circuit)
__device__ float edge_at(const float* img, const void* vmask, int b, int y, int x, int mode){
    if (y<3 || y>=HH-3 || x<3 || x>=WW-3) return 0.f;
    size_t vb = (size_t)b*HW;
    bool ok = true;
#pragma unroll
    for (int dy=-1;dy<=1;dy++)
#pragma unroll
        for (int dx=-1;dx<=1;dx++)
            ok &= readmask(vmask, vb + (size_t)(y+dy)*WW + (x+dx), mode);
    float sgx=0.f, sgy=0.f;
#pragma unroll
    for (int c=0;c<3;c++){
        const float* p = img + ((size_t)b*3 + c)*HW;
        float a00=p[(y-1)*WW+x-1], a01=p[(y-1)*WW+x], a02=p[(y-1)*WW+x+1];
        float a10=p[y*WW+x-1],                         a12=p[y*WW+x+1];
        float a20=p[(y+1)*WW+x-1], a21=p[(y+1)*WW+x], a22=p[(y+1)*WW+x+1];
        float gx = (a02 - a00) + 2.f*(a12 - a10) + (a22 - a20);
        float gy = (a20 - a00) + 2.f*(a21 - a01) + (a22 - a02);
        gx *= 0.125f; gy *= 0.125f;
        sgx += gx*gx; sgy += gy*gy;
    }
    float gxr = sqrtf(sgx/3.f);
    float gyr = sqrtf(sgy/3.f);
    return ok ? sqrtf(gxr*gxr + gyr*gyr) : 0.f;
}

__global__ __launch_bounds__(1024) void edge_topk_kernel(const float* image, const void* vmask){
    __shared__ unsigned long long key[2048];
    __shared__ unsigned shm[32];
    int b = blockIdx.x, tid = threadIdx.x;
    int mode = detect_mode<32>(vmask, shm);     // chain B independent of chain A
    if (tid==0){ g_epsum[b]=0.f; g_epcnt[b]=0u; }   // patch runs after us on same stream
    for (int j=tid;j<2048;j+=1024){
        unsigned long long kv = 0ull;
        if (j < NC){
            int oy = j/OW, ox = j%OW;
            float sy = (float)(480.0/34.0);
            float sx = (float)(640.0/45.0);
            float cyf = fminf(fmaxf(((float)oy + 0.5f)*sy - 0.5f, 0.f), (float)(HH-1));
            float cxf = fminf(fmaxf(((float)ox + 0.5f)*sx - 0.5f, 0.f), (float)(WW-1));
            int y0 = (int)floorf(cyf); int y1 = min(y0+1, HH-1); float wy = cyf - (float)y0;
            int x0 = (int)floorf(cxf); int x1 = min(x0+1, WW-1); float wx = cxf - (float)x0;
            float e00 = edge_at(image, vmask, b, y0, x0, mode);
            float e01 = edge_at(image, vmask, b, y0, x1, mode);
            float e10 = edge_at(image, vmask, b, y1, x0, mode);
            float e11 = edge_at(image, vmask, b, y1, x1, mode);
            float val = ((e00*(1.f-wy))*(1.f-wx)) + ((e01*(1.f-wy))*wx)
                      + ((e10*wy)*(1.f-wx)) + ((e11*wy)*wx);
            kv = ((unsigned long long)fkey(val) << 32) | (unsigned)(0xFFFFFFFFu - (unsigned)j);
        }
        key[j] = kv;
    }
    __syncthreads();
    for (int size=2; size<=2048; size<<=1){
        for (int stride=size>>1; stride>0; stride>>=1){
            for (int e=tid; e<2048; e+=1024){
                int p = e ^ stride;
                if (p > e){
                    bool up = (e & size)==0;
                    unsigned long long A = key[e], Bk = key[p];
                    bool sw = up ? (A < Bk) : (A > Bk);
                    if (sw){ key[e]=Bk; key[p]=A; }
                }
            }
            __syncthreads();
        }
    }
    if (tid < K_TOP){
        unsigned idx = 0xFFFFFFFFu - (unsigned)(key[tid] & 0xFFFFFFFFull);
        g_cy[b][tid] = (int)(idx/OW)*14;
        g_cx[b][tid] = (int)(idx%OW)*14;
    }
}

// warp-per-patch: independent loads (values loaded unconditionally, mask applied after)
__global__ __launch_bounds__(256) void patch_kernel(const float* inp, const float* tgt, const void* mask){
    __shared__ unsigned shm[8];
    int mode = detect_mode<8>(mask, shm);
    int b = blockIdx.y, w = threadIdx.x>>5, lane = threadIdx.x&31;
    int p = blockIdx.x*8 + w;
    if (p >= K_TOP) return;
    int cy = g_cy[b][p], cx = g_cx[b][p];
    unsigned ki[20], kt[20];
    unsigned mmb = 0;
    unsigned lc = 0;
#pragma unroll
    for (int s=0;s<20;s++){
        int i = s*32 + lane;
        float vi=0.f, vt=0.f;
        bool m = false;
        if (i < PS){
            int dy = i/KS - 12, dx = i%KS - 12;
            int y = cy+dy, x = cx+dx;
            if (y>=0 && y<HH && x>=0 && x<WW){
                size_t idx = (size_t)b*HW + (size_t)y*WW + x;
                m = readmask(mask, idx, mode);
                vi = inp[idx];      // unconditional: independent of mask load
                vt = tgt[idx];
            }
        }
        if (m){ mmb |= (1u<<s); lc++; } else { vi=0.f; vt=0.f; }
        ki[s] = fkey(vi); kt[s] = fkey(vt);
    }
    unsigned n = __reduce_add_sync(0xffffffffu, lc);

    float med0=0.f, med1=0.f;
    if (n){
        unsigned k = (n-1u)>>1;
        unsigned lo0=0u, hi0=0xFFFFFFFFu, lo1=0u, hi1=0xFFFFFFFFu;
        while (lo0 < hi0 || lo1 < hi1){
            unsigned mid0 = lo0 + ((hi0-lo0)>>1);
            unsigned mid1 = lo1 + ((hi1-lo1)>>1);
            unsigned c=0;
#pragma unroll
            for (int s=0;s<20;s++){
                if ((mmb>>s)&1u){
                    c += (ki[s] <= mid0) ? 1u : 0u;
                    c += (kt[s] <= mid1) ? 0x10000u : 0u;
                }
            }
            c = __reduce_add_sync(0xffffffffu, c);
            unsigned c0 = c & 0xFFFFu, c1 = c >> 16;
            if (lo0 < hi0){ if (c0 >= k+1u) hi0=mid0; else lo0=mid0+1u; }
            if (lo1 < hi1){ if (c1 >= k+1u) hi1=mid1; else lo1=mid1+1u; }
        }
        med0 = fval(hi0);
        med1 = fval(hi1);
    }

    float a0=0.f, a1=0.f;
#pragma unroll
    for (int s=0;s<20;s++){
        if ((mmb>>s)&1u){
            a0 += fabsf(fval(ki[s])-med0);
            a1 += fabsf(fval(kt[s])-med1);
        }
    }
    a0 = wRSumF(a0); a1 = wRSumF(a1);
    float fn = fmaxf((float)n, 1.f);
    float d0 = fmaxf(a0/fn, EPSV);
    float d1 = fmaxf(a1/fn, EPSV);
    float r0 = 1.f/d0, r1 = 1.f/d1;

    float e = 0.f;
#pragma unroll
    for (int s=0;s<20;s++){
        if ((mmb>>s)&1u){
            float gi = (fval(ki[s])-med0)*r0;
            float gt = (fval(kt[s])-med1)*r1;
            e += fmaxf(fabsf(gi-gt), EPSV);
        }
    }
    e = wRSumF(e);
    if (lane==0 && n>=4u){
        float ep = sqrtf(fmaxf(e/fn, EPSV));
        atomicAdd(&g_epsum[b], ep);
        atomicAdd(&g_epcnt[b], 1u);
    }
}

__global__ void final_kernel(float* out){
    int b = threadIdx.x;
    if (b >= BB) return;
    float ep = g_epsum[b] / fmaxf((float)g_epcnt[b], 1.f);
    float fn = fmaxf((float)g_ntot[0][b], 1.f);
    float eg = sqrtf(fmaxf(g_gsum[b]/fn, EPSV));
    out[b] = 0.5f*(ep + eg);
}

// ---------------- launch ----------------
extern "C" void kernel_launch(void* const* d_in, const int* in_sizes, int n_in,
                              void* d_out, int out_size) {
    const float* inp  = (const float*)d_in[0];
    const float* tgt  = (const float*)d_in[1];
    const void*  mask = d_in[2];
    const float* img  = (const float*)d_in[3];
    const void*  vmsk = d_in[4];
    float* out = (float*)d_out;

    static bool once = false;
    static cudaStream_t s2;
    static cudaEvent_t evFork, evJoin;
    if (!once){
        cudaFuncSetAttribute(sample_kernel, cudaFuncAttributeMaxDynamicSharedMemorySize, SAMP*4);
        cudaStreamCreateWithFlags(&s2, cudaStreamNonBlocking);
        cudaEventCreateWithFlags(&evFork, cudaEventDisableTiming);
        cudaEventCreateWithFlags(&evJoin, cudaEventDisableTiming);
        once = true;
    }

    // fork chain B at graph root (fully independent of chain A)
    cudaEventRecord(evFork, 0);
    cudaStreamWaitEvent(s2, evFork, 0);
    edge_topk_kernel<<<BB,1024,0,s2>>>(img, vmsk);
    patch_kernel<<<dim3((K_TOP+7)/8,BB),256,0,s2>>>(inp, tgt, mask);
    cudaEventRecord(evJoin, s2);

    // chain A on default stream
    sample_kernel<<<dim3(2,BB),256,SAMP*4>>>(inp, tgt, mask);
    passA_kernel<<<dim3(SEG,BB),256>>>(inp, tgt, mask);
    select_kernel<<<dim3(2,BB),256>>>();
    fallback_kernel<<<dim3(2,BB),256>>>(inp, tgt, mask);
    gerr_kernel<<<dim3(SEG,BB),256>>>(inp, tgt, mask);

    // join and finalize
    cudaStreamWaitEvent(0, evJoin, 0);
    final_kernel<<<1,32>>>(out);
}